// round 7
// baseline (speedup 1.0000x reference)
#include <cuda_runtime.h>
#include <cstdint>

#define S_      7
#define SS_     49
#define BATCH_  16384
#define D_      30
#define NCELL_  (BATCH_ * SS_)         /* 802816 */
#define CPB_    128                    /* cells per tile */
#define BLK_    192                    /* threads per block */
#define NBLK_   296                    /* persistent blocks = 2 x 148 SMs */
#define NT_     (NCELL_ / CPB_)        /* 6272 tiles */
#define TILE_W  (CPB_ * D_)            /* 3840 floats */
#define TILE_B  (TILE_W * 4)           /* 15360 bytes per tensor tile */
#define STAGE_W (TILE_W * 2)           /* so|st per stage */
#define STAGE_B (TILE_B * 2)           /* 30720 bytes */
#define NSTG_   3
#define SMEM_BYTES (NSTG_ * STAGE_B)   /* 92160 */
#define LPT_    5                      /* float4 per thread per tensor (960/192) */
#define OUT_BLKS_ 128
#define BPO_    128                    /* batches per output block */
#define OUT_V   (BPO_ * SS_ / 4)       /* 1568 float4 */

__device__ float g_A[SS_];
__device__ float g_C;
__device__ float g_has[NCELL_];
__device__ int   g_barrier;            /* static 0; self-resets */
__device__ int   g_done;               /* static 0; self-resets */

__device__ __forceinline__ float scalar_to_float(const void* p) {
    int v = *(const int*)p;
    if (v > 0 && v < 1000000) return (float)v;
    return __int_as_float(v);
}

__device__ __forceinline__ void cp16(uint32_t dst, const void* src) {
    asm volatile("cp.async.cg.shared.global [%0], [%1], 16;" :: "r"(dst), "l"(src));
}

__device__ __forceinline__ float iou_fn(float cx, float cy, float w, float h,
                                        float tx0, float ty0, float tx1, float ty1,
                                        float areaT) {
    float hw = w * 0.5f, hh = h * 0.5f;
    float x0 = cx - hw, x1 = cx + hw;
    float y0 = cy - hh, y1 = cy + hh;
    float iw = fmaxf(fminf(x1, tx1) - fmaxf(x0, tx0), 0.0f);
    float ih = fmaxf(fminf(y1, ty1) - fmaxf(y0, ty0), 0.0f);
    float inter = iw * ih;
    float area_a = (x1 - x0) * (y1 - y0);
    return inter / (area_a + areaT - inter + 1e-9f);
}

extern __shared__ float dynsmem[];

__global__ __launch_bounds__(BLK_) void yolo_kernel(
    const float* __restrict__ outp, const float* __restrict__ tgt,
    const void* __restrict__ iwp, const void* __restrict__ ihp,
    float* __restrict__ lossOut)
{
    __shared__ float sA_blk[SS_];
    __shared__ float sC_blk;
    __shared__ float sAfin[SS_ + 1];

    const float W = scalar_to_float(iwp);
    const float H = scalar_to_float(ihp);
    const float csx = W / 7.0f, csy = H / 7.0f;

    const int tid = threadIdx.x;
    const int bid = blockIdx.x;
    const uint32_t sbase = (uint32_t)__cvta_generic_to_shared(dynsmem);

    if (tid < SS_) sA_blk[tid] = 0.0f;
    if (tid == 64) sC_blk = 0.0f;

    /* my tiles: bid, bid+296, ...  (first 56 blocks get 22, rest 21) */
    const int nt = (NT_ - bid + NBLK_ - 1) / NBLK_;

    /* ---- issue helper inlined: stage s <- tile t ---- */
#define ISSUE_TILE(t, s) do {                                                 \
        const float4* go4 = (const float4*)(outp + (size_t)(t) * TILE_W);     \
        const float4* gt4 = (const float4*)(tgt  + (size_t)(t) * TILE_W);     \
        uint32_t so_s = sbase + (s) * STAGE_B;                                \
        uint32_t st_s = so_s + TILE_B;                                        \
        _Pragma("unroll")                                                     \
        for (int j = 0; j < LPT_; j++) {                                      \
            int idx = j * BLK_ + tid;                                         \
            cp16(so_s + idx * 16, go4 + idx);                                 \
            cp16(st_s + idx * 16, gt4 + idx);                                 \
        }                                                                     \
        asm volatile("cp.async.commit_group;");                               \
    } while (0)

    /* prefetch stages 0,1 */
    ISSUE_TILE(bid, 0);
    ISSUE_TILE(bid + NBLK_, 1);

    float accC = 0.0f;

    for (int k = 0; k < nt; k++) {
        /* issue tile k+2 (or empty group to keep accounting) */
        if (k + 2 < nt) {
            ISSUE_TILE(bid + (k + 2) * NBLK_, (k + 2) % NSTG_);
        } else {
            asm volatile("cp.async.commit_group;");
        }
        asm volatile("cp.async.wait_group 2;");
        __syncthreads();                    /* stage k%3 fully landed */

        const int stg = k % NSTG_;
        const float* so = dynsmem + stg * STAGE_W;
        const float* st = so + TILE_W;

        if (tid < CPB_) {
            const int cell = (bid + k * NBLK_) * CPB_ + tid;
            const int rc = cell % SS_;
            const float rr = (float)(rc / S_);
            const float cc = (float)(rc % S_);

            const float2* o2 = (const float2*)(so + tid * D_);
            const float2* t2 = (const float2*)(st + tid * D_);

            float2 oa = o2[0], ob = o2[1], oc = o2[2], od = o2[3], oe = o2[4];
            float2 ta = t2[0], tb = t2[1], tc = t2[2];

            float o0 = oa.x, o1 = oa.y, o3 = ob.y, o4 = oc.x;
            float o5 = oc.y, o6 = od.x, o8 = oe.x, o9 = oe.y;

            float tx = ta.x, ty = ta.y;
            float tw = tb.x * W, th = tb.y * H;
            float has = tc.x;

            float cxt = (cc + tx) * csx, cyt = (rr + ty) * csy;
            float htw = tw * 0.5f, hth = th * 0.5f;
            float tx0 = cxt - htw, tx1 = cxt + htw;
            float ty0 = cyt - hth, ty1 = cyt + hth;
            float areaT = (tx1 - tx0) * (ty1 - ty0);

            float iou0 = iou_fn((cc + o0) * csx, (rr + o1) * csy, o3 * W, o4 * H,
                                tx0, ty0, tx1, ty1, areaT);
            float iou1 = iou_fn((cc + o5) * csx, (rr + o6) * csy, o8 * W, o9 * H,
                                tx0, ty0, tx1, ty1, areaT);

            float bc = (iou1 >= iou0) ? o9 : o4;    /* last argmax per reference */

            float cls = 0.0f;
#pragma unroll
            for (int kk = 0; kk < 10; kk++) {
                float2 ock = o2[5 + kk];
                float2 tck = t2[5 + kk];
                float d0 = tck.x - ock.x * bc;
                float d1 = tck.y - ock.y * bc;
                cls += d0 * d0 + d1 * d1;
            }

            float dx  = tx - o5;
            float dy  = ty - o6;
            float swd = sqrtf(tw) - sqrtf(o8 * W);
            float shd = sqrtf(th) - sqrtf(o9 * H);
            float dcf = has - o9;
            float confsq = dcf * dcf;

            float accA = 5.0f * (dx * dx + dy * dy + swd * swd + shd * shd)
                       + 0.5f * confsq;
            accC += 0.5f * confsq + cls;

            g_has[cell] = has;
            atomicAdd(&sA_blk[rc], accA);
        }
        __syncthreads();                    /* stage reusable next iteration */
    }

    /* block reduction of C */
#pragma unroll
    for (int off = 16; off > 0; off >>= 1)
        accC += __shfl_down_sync(0xFFFFFFFFu, accC, off);
    if ((tid & 31) == 0) atomicAdd(&sC_blk, accC);
    __syncthreads();

    if (tid < SS_) atomicAdd(&g_A[tid], sA_blk[tid]);
    if (tid == 64) atomicAdd(&g_C, sC_blk);

    /* ---------------- grid-wide barrier ---------------- */
    __threadfence();                        /* every thread: g_has visible */
    __syncthreads();
    if (tid == 0) {
        atomicAdd(&g_barrier, 1);
        while (*(volatile int*)&g_barrier < NBLK_) { __nanosleep(64); }
    }
    __syncthreads();

    /* ---------------- phase 2: per-batch outputs ---------------- */
    int arrive_old;
    if (bid < OUT_BLKS_) {
        if (tid < SS_) sAfin[tid] = g_A[tid];
        if (tid == 64) sAfin[SS_] = g_C;

        const float4* gh4 = (const float4*)(g_has + (size_t)bid * BPO_ * SS_);
        float4* sh4 = (float4*)dynsmem;
#pragma unroll
        for (int j = 0; j < 9; j++) {
            int idx = j * BLK_ + tid;
            if (idx < OUT_V) sh4[idx] = gh4[idx];
        }
        __syncthreads();

        if (tid == 0) arrive_old = atomicAdd(&g_done, 1);

        if (tid < BPO_) {
            const float* hb = dynsmem + tid * SS_;   /* stride 49: conflict-free */
            float s = 0.0f;
#pragma unroll
            for (int rc = 0; rc < SS_; rc++)
                s += hb[rc] * sAfin[rc];
            lossOut[bid * BPO_ + tid] = s + sAfin[SS_];
        }
    } else {
        if (tid == 0) arrive_old = atomicAdd(&g_done, 1);
    }

    if (tid == 0 && arrive_old == NBLK_ - 1) {
#pragma unroll
        for (int i = 0; i < SS_; i++) g_A[i] = 0.0f;
        g_C = 0.0f;
        g_barrier = 0;
        g_done = 0;
    }
}

extern "C" void kernel_launch(void* const* d_in, const int* in_sizes, int n_in,
                              void* d_out, int out_size)
{
    const float* o  = (const float*)d_in[0];
    const float* t  = (const float*)d_in[1];
    const void*  iw = d_in[2];
    const void*  ih = d_in[3];

    cudaFuncSetAttribute(yolo_kernel,
                         cudaFuncAttributeMaxDynamicSharedMemorySize, SMEM_BYTES);
    yolo_kernel<<<NBLK_, BLK_, SMEM_BYTES>>>(o, t, iw, ih, (float*)d_out);
}

// round 9
// speedup vs baseline: 1.0567x; 1.0567x over previous
#include <cuda_runtime.h>
#include <cstdint>

#define S_      7
#define SS_     49
#define BATCH_  16384
#define D_      30
#define NCELL_  (BATCH_ * SS_)         /* 802816 */
#define CPB_    128                    /* cells per tile */
#define BLK_    192                    /* threads per block */
#define NBLK_   296                    /* persistent blocks = 2 x 148 SMs */
#define NT_     (NCELL_ / CPB_)        /* 6272 tiles */
#define TILE_W  (CPB_ * D_)            /* 3840 floats */
#define TILE_B  (TILE_W * 4)           /* 15360 bytes per tensor tile */
#define STAGE_W (TILE_W * 2)
#define STAGE_B (TILE_B * 2)           /* 30720 bytes */
#define NSTG_   3
#define SMEM_BYTES (NSTG_ * STAGE_B)   /* 92160 */
#define LPT_    5                      /* float4 per thread per tensor */
#define RCSTEP_ 11                     /* (NBLK_*CPB_) % 49 */
#define OUT_BLKS_ 256                  /* phase-2 blocks */
#define BPO_    64                     /* batches per out block; 256*64 = 16384 */
#define OUT_V   (BPO_ * SS_ / 4)       /* 784 float4; 64*49*4 B is 16B-aligned */

__device__ float g_A[SS_];
__device__ float g_C;
__device__ float g_has[NCELL_];
__device__ int   g_barrier;            /* static 0; self-resets */
__device__ int   g_done;               /* static 0; self-resets */

__device__ __forceinline__ float scalar_to_float(const void* p) {
    int v = *(const int*)p;
    if (v > 0 && v < 1000000) return (float)v;
    return __int_as_float(v);
}

__device__ __forceinline__ void cp16(uint32_t dst, const void* src) {
    asm volatile("cp.async.cg.shared.global [%0], [%1], 16;" :: "r"(dst), "l"(src));
}

__device__ __forceinline__ float iou_fn(float cx, float cy, float w, float h,
                                        float tx0, float ty0, float tx1, float ty1,
                                        float areaT) {
    float hw = w * 0.5f, hh = h * 0.5f;
    float x0 = cx - hw, x1 = cx + hw;
    float y0 = cy - hh, y1 = cy + hh;
    float iw = fmaxf(fminf(x1, tx1) - fmaxf(x0, tx0), 0.0f);
    float ih = fmaxf(fminf(y1, ty1) - fmaxf(y0, ty0), 0.0f);
    float inter = iw * ih;
    float area_a = (x1 - x0) * (y1 - y0);
    return inter / (area_a + areaT - inter + 1e-9f);
}

extern __shared__ float dynsmem[];

__global__ __launch_bounds__(BLK_) void yolo_kernel(
    const float* __restrict__ outp, const float* __restrict__ tgt,
    const void* __restrict__ iwp, const void* __restrict__ ihp,
    float* __restrict__ lossOut)
{
    __shared__ float sA_blk[SS_];
    __shared__ float sC_blk;
    __shared__ float sAfin[SS_ + 1];

    const float W = scalar_to_float(iwp);
    const float H = scalar_to_float(ihp);
    const float csx = W / 7.0f, csy = H / 7.0f;

    const int tid = threadIdx.x;
    const int bid = blockIdx.x;
    const uint32_t sbase = (uint32_t)__cvta_generic_to_shared(dynsmem);

    if (tid < SS_) sA_blk[tid] = 0.0f;
    if (tid == 64) sC_blk = 0.0f;

    const int nt = (NT_ - bid + NBLK_ - 1) / NBLK_;   /* 21 or 22 tiles */

    /* hoisted per-thread source/dest offsets for the copy loops */
    const float4* gobase = (const float4*)outp + (size_t)bid * (TILE_W / 4);
    const float4* gtbase = (const float4*)tgt  + (size_t)bid * (TILE_W / 4);
    const uint32_t sdst0 = sbase + tid * 16;

#define ISSUE_TILE(k, s) do {                                                 \
        const float4* go4 = gobase + (size_t)(k) * (NBLK_ * TILE_W / 4);      \
        const float4* gt4 = gtbase + (size_t)(k) * (NBLK_ * TILE_W / 4);      \
        uint32_t so_s = sdst0 + (s) * STAGE_B;                                \
        _Pragma("unroll")                                                     \
        for (int j = 0; j < LPT_; j++) {                                      \
            cp16(so_s + j * (BLK_ * 16),          go4 + j * BLK_ + tid);      \
            cp16(so_s + TILE_B + j * (BLK_ * 16), gt4 + j * BLK_ + tid);      \
        }                                                                     \
        asm volatile("cp.async.commit_group;");                               \
    } while (0)

    ISSUE_TILE(0, 0);
    ISSUE_TILE(1, 1);

    float accC = 0.0f;
    /* rc of this thread's first cell; advances by +11 mod 49 each tile */
    int rc = (bid * CPB_ + tid) % SS_;

    for (int k = 0; k < nt; k++) {
        if (k + 2 < nt) {
            ISSUE_TILE(k + 2, (k + 2) % NSTG_);
        } else {
            asm volatile("cp.async.commit_group;");
        }
        asm volatile("cp.async.wait_group 2;");
        __syncthreads();

        const int stg = k % NSTG_;
        const float* so = dynsmem + stg * STAGE_W;
        const float* st = so + TILE_W;

        if (tid < CPB_) {
            const int cell = (bid + k * NBLK_) * CPB_ + tid;
            const float rr = (float)(rc / S_);
            const float cc = (float)(rc - (rc / S_) * S_);

            const float2* o2 = (const float2*)(so + tid * D_);
            const float2* t2 = (const float2*)(st + tid * D_);

            float2 oa = o2[0], ob = o2[1], oc = o2[2], od = o2[3], oe = o2[4];
            float2 ta = t2[0], tb = t2[1], tc = t2[2];

            float o0 = oa.x, o1 = oa.y, o3 = ob.y, o4 = oc.x;
            float o5 = oc.y, o6 = od.x, o8 = oe.x, o9 = oe.y;

            float tx = ta.x, ty = ta.y;
            float tw = tb.x * W, th = tb.y * H;
            float has = tc.x;

            g_has[cell] = has;

            float cxt = (cc + tx) * csx, cyt = (rr + ty) * csy;
            float htw = tw * 0.5f, hth = th * 0.5f;
            float tx0 = cxt - htw, tx1 = cxt + htw;
            float ty0 = cyt - hth, ty1 = cyt + hth;
            float areaT = (tx1 - tx0) * (ty1 - ty0);

            float iou0 = iou_fn((cc + o0) * csx, (rr + o1) * csy, o3 * W, o4 * H,
                                tx0, ty0, tx1, ty1, areaT);
            float iou1 = iou_fn((cc + o5) * csx, (rr + o6) * csy, o8 * W, o9 * H,
                                tx0, ty0, tx1, ty1, areaT);

            float bc = (iou1 >= iou0) ? o9 : o4;   /* last argmax per reference */

            float cls = 0.0f;
#pragma unroll
            for (int kk = 0; kk < 10; kk++) {
                float2 ock = o2[5 + kk];
                float2 tck = t2[5 + kk];
                float d0 = tck.x - ock.x * bc;
                float d1 = tck.y - ock.y * bc;
                cls += d0 * d0 + d1 * d1;
            }

            float dx  = tx - o5;
            float dy  = ty - o6;
            float swd = sqrtf(tw) - sqrtf(o8 * W);
            float shd = sqrtf(th) - sqrtf(o9 * H);
            float dcf = has - o9;
            float confsq = dcf * dcf;

            float accA = 5.0f * (dx * dx + dy * dy + swd * swd + shd * shd)
                       + 0.5f * confsq;
            accC += 0.5f * confsq + cls;

            atomicAdd(&sA_blk[rc], accA);

            rc += RCSTEP_;
            if (rc >= SS_) rc -= SS_;
        }
        __syncthreads();
    }

    /* block reduction of C */
#pragma unroll
    for (int off = 16; off > 0; off >>= 1)
        accC += __shfl_down_sync(0xFFFFFFFFu, accC, off);
    if ((tid & 31) == 0) atomicAdd(&sC_blk, accC);
    __syncthreads();

    if (tid < SS_) atomicAdd(&g_A[tid], sA_blk[tid]);
    if (tid == 64) atomicAdd(&g_C, sC_blk);

    /* ---------------- grid-wide barrier ---------------- */
    __threadfence();                        /* every thread: g_has visible */
    __syncthreads();
    if (tid == 0) {
        atomicAdd(&g_barrier, 1);
        while (*(volatile int*)&g_barrier < NBLK_) { __nanosleep(32); }
    }
    __syncthreads();

    /* ---------------- phase 2: 256 blocks x 64 batches ---------------- */
    int arrive_old = 0;
    if (bid < OUT_BLKS_) {
        if (tid < SS_) sAfin[tid] = g_A[tid];
        if (tid == 64) sAfin[SS_] = g_C;

        /* start = bid*64 -> byte offset bid*12544, 16B-aligned for float4 */
        const float4* gh4 = (const float4*)(g_has + (size_t)bid * BPO_ * SS_);
        float4* sh4 = (float4*)dynsmem;
#pragma unroll
        for (int j = 0; j < 5; j++) {
            int idx = j * BLK_ + tid;
            if (idx < OUT_V) sh4[idx] = gh4[idx];
        }
        __syncthreads();                    /* latch + stage complete */

        if (tid == 0) arrive_old = atomicAdd(&g_done, 1);

        if (tid < BPO_) {
            const float* hb = dynsmem + tid * SS_;   /* stride 49: conflict-free */
            float s = 0.0f;
#pragma unroll
            for (int r = 0; r < SS_; r++)
                s += hb[r] * sAfin[r];
            lossOut[bid * BPO_ + tid] = s + sAfin[SS_];
        }
    } else {
        if (tid == 0) arrive_old = atomicAdd(&g_done, 1);
    }

    /* last arriving block resets accumulators for the next replay */
    if (tid == 0 && arrive_old == NBLK_ - 1) {
#pragma unroll
        for (int i = 0; i < SS_; i++) g_A[i] = 0.0f;
        g_C = 0.0f;
        g_barrier = 0;
        g_done = 0;
    }
}

extern "C" void kernel_launch(void* const* d_in, const int* in_sizes, int n_in,
                              void* d_out, int out_size)
{
    const float* o  = (const float*)d_in[0];
    const float* t  = (const float*)d_in[1];
    const void*  iw = d_in[2];
    const void*  ih = d_in[3];

    cudaFuncSetAttribute(yolo_kernel,
                         cudaFuncAttributeMaxDynamicSharedMemorySize, SMEM_BYTES);
    yolo_kernel<<<NBLK_, BLK_, SMEM_BYTES>>>(o, t, iw, ih, (float*)d_out);
}

// round 13
// speedup vs baseline: 1.0666x; 1.0094x over previous
#include <cuda_runtime.h>
#include <cstdint>

#define S_      7
#define SS_     49
#define BATCH_  16384
#define D_      30
#define NCELL_  (BATCH_ * SS_)         /* 802816 */
#define CPB_    128                    /* cells per tile */
#define BLK_    192                    /* threads per block */
#define NBLK_   296                    /* persistent blocks = 2 x 148 SMs */
#define NT_     (NCELL_ / CPB_)        /* 6272 tiles */
#define TILE_W  (CPB_ * D_)            /* 3840 floats */
#define TILE_B  (TILE_W * 4)           /* 15360 bytes per tensor tile */
#define STAGE_W (TILE_W * 2)
#define STAGE_B (TILE_B * 2)           /* 30720 bytes */
#define NSTG_   3
#define SMEM_BYTES (NSTG_ * STAGE_B)   /* 92160 */
#define RCSTEP_ 11                     /* (NBLK_*CPB_) % 49 */
#define OUT_BLKS_ 256
#define BPO_    64                     /* 256*64 = 16384; 64*49*4B 16B-aligned */
#define OUT_V   (BPO_ * SS_ / 4)       /* 784 float4 */

__device__ float g_A[SS_];
__device__ float g_C;
__device__ float g_has[NCELL_];
__device__ int   g_barrier;            /* static 0; self-resets */
__device__ int   g_done;               /* static 0; self-resets */

__device__ __forceinline__ float scalar_to_float(const void* p) {
    int v = *(const int*)p;
    if (v > 0 && v < 1000000) return (float)v;
    return __int_as_float(v);
}

__device__ __forceinline__ float iou_fn(float cx, float cy, float w, float h,
                                        float tx0, float ty0, float tx1, float ty1,
                                        float areaT) {
    float hw = w * 0.5f, hh = h * 0.5f;
    float x0 = cx - hw, x1 = cx + hw;
    float y0 = cy - hh, y1 = cy + hh;
    float iw = fmaxf(fminf(x1, tx1) - fmaxf(x0, tx0), 0.0f);
    float ih = fmaxf(fminf(y1, ty1) - fmaxf(y0, ty0), 0.0f);
    float inter = iw * ih;
    float area_a = (x1 - x0) * (y1 - y0);
    return inter / (area_a + areaT - inter + 1e-9f);
}

__device__ __forceinline__ void mbar_init(uint32_t mbar, uint32_t cnt) {
    asm volatile("mbarrier.init.shared.b64 [%0], %1;" :: "r"(mbar), "r"(cnt) : "memory");
}
__device__ __forceinline__ void mbar_expect_tx(uint32_t mbar, uint32_t bytes) {
    asm volatile("mbarrier.arrive.expect_tx.shared.b64 _, [%0], %1;"
                 :: "r"(mbar), "r"(bytes) : "memory");
}
__device__ __forceinline__ void bulk_g2s(uint32_t dst, const void* src,
                                         uint32_t bytes, uint32_t mbar) {
    asm volatile("cp.async.bulk.shared::cluster.global.mbarrier::complete_tx::bytes "
                 "[%0], [%1], %2, [%3];"
                 :: "r"(dst), "l"(src), "r"(bytes), "r"(mbar) : "memory");
}
__device__ __forceinline__ void mbar_wait(uint32_t mbar, uint32_t parity) {
    uint32_t done;
    asm volatile("{\n\t.reg .pred p;\n\t"
                 "mbarrier.try_wait.parity.acquire.cta.shared::cta.b64 p, [%1], %2;\n\t"
                 "selp.b32 %0, 1, 0, p;\n\t}"
                 : "=r"(done) : "r"(mbar), "r"(parity) : "memory");
    if (!done) {
        asm volatile("{\n\t.reg .pred P1;\n\t"
                     "WL_%=:\n\t"
                     "mbarrier.try_wait.parity.acquire.cta.shared::cta.b64 P1, [%0], %1, 0x989680;\n\t"
                     "@P1 bra.uni WD_%=;\n\t"
                     "bra.uni WL_%=;\n\t"
                     "WD_%=:\n\t}"
                     :: "r"(mbar), "r"(parity) : "memory");
    }
}

extern __shared__ float dynsmem[];

__global__ __launch_bounds__(BLK_) void yolo_kernel(
    const float* __restrict__ outp, const float* __restrict__ tgt,
    const void* __restrict__ iwp, const void* __restrict__ ihp,
    float* __restrict__ lossOut)
{
    __shared__ __align__(8) unsigned long long mbar_store[NSTG_];
    __shared__ float sA_blk[SS_];
    __shared__ float sC_blk;
    __shared__ float sAfin[SS_ + 1];

    const float W = scalar_to_float(iwp);
    const float H = scalar_to_float(ihp);
    const float csx = W / 7.0f, csy = H / 7.0f;

    const int tid = threadIdx.x;
    const int bid = blockIdx.x;
    const uint32_t sbase = (uint32_t)__cvta_generic_to_shared(dynsmem);
    const uint32_t mb0   = (uint32_t)__cvta_generic_to_shared(mbar_store);

    if (tid < SS_) sA_blk[tid] = 0.0f;
    if (tid == 64) sC_blk = 0.0f;
    if (tid == 0) {
#pragma unroll
        for (int s = 0; s < NSTG_; s++) mbar_init(mb0 + s * 8, 1);
        asm volatile("fence.proxy.async.shared::cta;" ::: "memory");
    }
    __syncthreads();

    const int nt = (NT_ - bid + NBLK_ - 1) / NBLK_;   /* 21 or 22 tiles */

    const char* gob = (const char*)(outp + (size_t)bid * TILE_W);
    const char* gtb = (const char*)(tgt  + (size_t)bid * TILE_W);

#define ISSUE_TILE(k, s) do {                                                  \
        uint32_t bar = mb0 + (s) * 8;                                          \
        uint32_t dst = sbase + (s) * STAGE_B;                                  \
        mbar_expect_tx(bar, STAGE_B);                                          \
        bulk_g2s(dst,          gob + (size_t)(k) * (NBLK_ * TILE_B), TILE_B, bar); \
        bulk_g2s(dst + TILE_B, gtb + (size_t)(k) * (NBLK_ * TILE_B), TILE_B, bar); \
    } while (0)

    if (tid == 0) {
        ISSUE_TILE(0, 0);
        ISSUE_TILE(1, 1);
    }

    float accC = 0.0f;
    int rc = (bid * CPB_ + tid) % SS_;     /* advances +11 mod 49 per tile */

    for (int k = 0; k < nt; k++) {
        /* refill stage (k+2)%3: safe, tile k-1's readers left it last iter */
        if (tid == 0 && k + 2 < nt) ISSUE_TILE(k + 2, (k + 2) % NSTG_);

        const int stg = k % NSTG_;
        mbar_wait(mb0 + stg * 8, (k / 3) & 1);

        const float* so = dynsmem + stg * STAGE_W;
        const float* st = so + TILE_W;

        if (tid < CPB_) {
            const int cell = (bid + k * NBLK_) * CPB_ + tid;
            const float rr = (float)(rc / S_);
            const float cc = (float)(rc - (rc / S_) * S_);

            const float2* o2 = (const float2*)(so + tid * D_);
            const float2* t2 = (const float2*)(st + tid * D_);

            float2 oa = o2[0], ob = o2[1], oc = o2[2], od = o2[3], oe = o2[4];
            float2 ta = t2[0], tb = t2[1], tc = t2[2];

            float o0 = oa.x, o1 = oa.y, o3 = ob.y, o4 = oc.x;
            float o5 = oc.y, o6 = od.x, o8 = oe.x, o9 = oe.y;

            float tx = ta.x, ty = ta.y;
            float tw = tb.x * W, th = tb.y * H;
            float has = tc.x;

            g_has[cell] = has;

            float cxt = (cc + tx) * csx, cyt = (rr + ty) * csy;
            float htw = tw * 0.5f, hth = th * 0.5f;
            float tx0 = cxt - htw, tx1 = cxt + htw;
            float ty0 = cyt - hth, ty1 = cyt + hth;
            float areaT = (tx1 - tx0) * (ty1 - ty0);

            float iou0 = iou_fn((cc + o0) * csx, (rr + o1) * csy, o3 * W, o4 * H,
                                tx0, ty0, tx1, ty1, areaT);
            float iou1 = iou_fn((cc + o5) * csx, (rr + o6) * csy, o8 * W, o9 * H,
                                tx0, ty0, tx1, ty1, areaT);

            float bc = (iou1 >= iou0) ? o9 : o4;   /* last argmax per reference */

            float cls = 0.0f;
#pragma unroll
            for (int kk = 0; kk < 10; kk++) {
                float2 ock = o2[5 + kk];
                float2 tck = t2[5 + kk];
                float d0 = tck.x - ock.x * bc;
                float d1 = tck.y - ock.y * bc;
                cls += d0 * d0 + d1 * d1;
            }

            float dx  = tx - o5;
            float dy  = ty - o6;
            float swd = sqrtf(tw) - sqrtf(o8 * W);
            float shd = sqrtf(th) - sqrtf(o9 * H);
            float dcf = has - o9;
            float confsq = dcf * dcf;

            float accA = 5.0f * (dx * dx + dy * dy + swd * swd + shd * shd)
                       + 0.5f * confsq;
            accC += 0.5f * confsq + cls;

            atomicAdd(&sA_blk[rc], accA);

            rc += RCSTEP_;
            if (rc >= SS_) rc -= SS_;
        }
        __syncthreads();                   /* stage readers done -> reusable */
    }

    /* block reduction of C */
#pragma unroll
    for (int off = 16; off > 0; off >>= 1)
        accC += __shfl_down_sync(0xFFFFFFFFu, accC, off);
    if ((tid & 31) == 0) atomicAdd(&sC_blk, accC);
    __syncthreads();

    if (tid < SS_) atomicAdd(&g_A[tid], sA_blk[tid]);
    if (tid == 64) atomicAdd(&g_C, sC_blk);

    /* ---------------- grid-wide barrier ---------------- */
    __threadfence();
    __syncthreads();
    if (tid == 0) {
        atomicAdd(&g_barrier, 1);
        while (*(volatile int*)&g_barrier < NBLK_) { __nanosleep(32); }
    }
    __syncthreads();

    /* ---------------- phase 2: 256 blocks x 64 batches ---------------- */
    int arrive_old = 0;
    if (bid < OUT_BLKS_) {
        if (tid < SS_) sAfin[tid] = g_A[tid];
        if (tid == 64) sAfin[SS_] = g_C;

        const float4* gh4 = (const float4*)(g_has + (size_t)bid * BPO_ * SS_);
        float4* sh4 = (float4*)dynsmem;
#pragma unroll
        for (int j = 0; j < 5; j++) {
            int idx = j * BLK_ + tid;
            if (idx < OUT_V) sh4[idx] = gh4[idx];
        }
        __syncthreads();

        if (tid == 0) arrive_old = atomicAdd(&g_done, 1);

        if (tid < BPO_) {
            const float* hb = dynsmem + tid * SS_;   /* stride 49: conflict-free */
            float s = 0.0f;
#pragma unroll
            for (int r = 0; r < SS_; r++)
                s += hb[r] * sAfin[r];
            lossOut[bid * BPO_ + tid] = s + sAfin[SS_];
        }
    } else {
        if (tid == 0) arrive_old = atomicAdd(&g_done, 1);
    }

    if (tid == 0 && arrive_old == NBLK_ - 1) {
#pragma unroll
        for (int i = 0; i < SS_; i++) g_A[i] = 0.0f;
        g_C = 0.0f;
        g_barrier = 0;
        g_done = 0;
    }
}

extern "C" void kernel_launch(void* const* d_in, const int* in_sizes, int n_in,
                              void* d_out, int out_size)
{
    const float* o  = (const float*)d_in[0];
    const float* t  = (const float*)d_in[1];
    const void*  iw = d_in[2];
    const void*  ih = d_in[3];

    cudaFuncSetAttribute(yolo_kernel,
                         cudaFuncAttributeMaxDynamicSharedMemorySize, SMEM_BYTES);
    yolo_kernel<<<NBLK_, BLK_, SMEM_BYTES>>>(o, t, iw, ih, (float*)d_out);
}